// round 4
// baseline (speedup 1.0000x reference)
#include <cuda_runtime.h>
#include <cuda_fp16.h>
#include <math.h>
#include <float.h>
#include <stdint.h>

#define BDIM 2
#define NSEG 256
#define HID 1024
#define HID2 512
#define NCLS 6
#define NROWS 512
#define NPAIRS 131072

// ---------------- scratch ----------------
__device__ float g_a[NROWS*HID];
__device__ float g_b[NROWS*HID];
__device__ float g_h1[NROWS*HID];
__device__ float g_h2[NROWS*HID2];        // RAW accum (pre-bias, pre-relu)
__device__ float g_hatp[NROWS*NCLS];
__device__ float g_loss1_terms[NROWS];
__device__ int   g_segy[NROWS];
__device__ float g_logit[NPAIRS*2];
__device__ float g_q1[NPAIRS];
__device__ float g_loss2_part[512];
__device__ __half g_ws2t[HID2*HID];       // [n][k] fp16 (transposed Ws2)

// ---------------- helpers ----------------
__device__ __forceinline__ unsigned f2tf32(float x) {
    unsigned r;
    asm("cvt.rna.tf32.f32 %0, %1;" : "=r"(r) : "f"(x));
    return r;
}
__device__ __forceinline__ void mma8(float* d, const unsigned* a, const unsigned* b) {
    asm volatile(
        "mma.sync.aligned.m16n8k8.row.col.f32.tf32.tf32.f32 "
        "{%0,%1,%2,%3}, {%4,%5,%6,%7}, {%8,%9}, {%0,%1,%2,%3};\n"
        : "+f"(d[0]), "+f"(d[1]), "+f"(d[2]), "+f"(d[3])
        : "r"(a[0]), "r"(a[1]), "r"(a[2]), "r"(a[3]), "r"(b[0]), "r"(b[1]));
}
__device__ __forceinline__ void mma16(float* d, const unsigned* a, const unsigned* b) {
    asm volatile(
        "mma.sync.aligned.m16n8k16.row.col.f32.f16.f16.f32 "
        "{%0,%1,%2,%3}, {%4,%5,%6,%7}, {%8,%9}, {%0,%1,%2,%3};\n"
        : "+f"(d[0]), "+f"(d[1]), "+f"(d[2]), "+f"(d[3])
        : "r"(a[0]), "r"(a[1]), "r"(a[2]), "r"(a[3]), "r"(b[0]), "r"(b[1]));
}
__device__ __forceinline__ unsigned packh2(float lo, float hi) {
    __half2 h = __floats2half2_rn(lo, hi);
    return *reinterpret_cast<unsigned*>(&h);
}

#define SA_LD 36
#define SB_LD 136

// ---------------- generic tf32 GEMM body (128x128 tile) ----------------
// mode: 0 = store (+bias), 1 = store (+bias, relu), 2 = atomicAdd raw
__device__ __forceinline__ void gemm_body(
    const float* __restrict__ A, int lda, const float* __restrict__ B, int ldb,
    float* __restrict__ C, int ldc, const float* __restrict__ bias,
    int kbeg, int kend, int m0, int n0, int mode, unsigned* sA, unsigned* sB)
{
    int tid = threadIdx.x;
    int lane = tid & 31, warp = tid >> 5;
    int wm = warp & 3, wn = warp >> 2;

    float acc[2][8][4];
    #pragma unroll
    for (int a = 0; a < 2; a++)
        #pragma unroll
        for (int b_ = 0; b_ < 8; b_++)
            #pragma unroll
            for (int c = 0; c < 4; c++) acc[a][b_][c] = 0.f;

    for (int k0 = kbeg; k0 < kend; k0 += 32) {
        __syncthreads();
        #pragma unroll
        for (int s = tid; s < 1024; s += 256) {
            int row = s >> 3, cv = (s & 7) << 2;
            float4 v = *(const float4*)(A + (long)(m0 + row) * lda + k0 + cv);
            unsigned* p = &sA[row * SA_LD + cv];
            p[0] = f2tf32(v.x); p[1] = f2tf32(v.y); p[2] = f2tf32(v.z); p[3] = f2tf32(v.w);
        }
        #pragma unroll
        for (int s = tid; s < 1024; s += 256) {
            int row = s >> 5, cv = (s & 31) << 2;
            float4 v = *(const float4*)(B + (long)(k0 + row) * ldb + n0 + cv);
            unsigned* p = &sB[row * SB_LD + cv];
            p[0] = f2tf32(v.x); p[1] = f2tf32(v.y); p[2] = f2tf32(v.z); p[3] = f2tf32(v.w);
        }
        __syncthreads();
        #pragma unroll
        for (int ks = 0; ks < 4; ks++) {
            int k = ks << 3;
            unsigned af[2][4], bf[8][2];
            #pragma unroll
            for (int mi = 0; mi < 2; mi++) {
                int r = wm * 32 + mi * 16 + (lane >> 2);
                int c = k + (lane & 3);
                af[mi][0] = sA[r * SA_LD + c];
                af[mi][1] = sA[(r + 8) * SA_LD + c];
                af[mi][2] = sA[r * SA_LD + c + 4];
                af[mi][3] = sA[(r + 8) * SA_LD + c + 4];
            }
            #pragma unroll
            for (int ni = 0; ni < 8; ni++) {
                int c = wn * 64 + ni * 8 + (lane >> 2);
                int r = k + (lane & 3);
                bf[ni][0] = sB[r * SB_LD + c];
                bf[ni][1] = sB[(r + 4) * SB_LD + c];
            }
            #pragma unroll
            for (int mi = 0; mi < 2; mi++)
                #pragma unroll
                for (int ni = 0; ni < 8; ni++)
                    mma8(acc[mi][ni], af[mi], bf[ni]);
        }
    }

    #pragma unroll
    for (int mi = 0; mi < 2; mi++)
        #pragma unroll
        for (int ni = 0; ni < 8; ni++) {
            int r = m0 + wm * 32 + mi * 16 + (lane >> 2);
            int c = n0 + wn * 64 + ni * 8 + ((lane & 3) << 1);
            if (mode == 2) {
                atomicAdd(&C[(long)r * ldc + c],           acc[mi][ni][0]);
                atomicAdd(&C[(long)r * ldc + c + 1],       acc[mi][ni][1]);
                atomicAdd(&C[(long)(r + 8) * ldc + c],     acc[mi][ni][2]);
                atomicAdd(&C[(long)(r + 8) * ldc + c + 1], acc[mi][ni][3]);
            } else {
                float b0 = bias ? bias[c] : 0.f;
                float b1 = bias ? bias[c + 1] : 0.f;
                float v0 = acc[mi][ni][0] + b0, v1 = acc[mi][ni][1] + b1;
                float v2 = acc[mi][ni][2] + b0, v3 = acc[mi][ni][3] + b1;
                if (mode == 1) {
                    v0 = fmaxf(v0, 0.f); v1 = fmaxf(v1, 0.f);
                    v2 = fmaxf(v2, 0.f); v3 = fmaxf(v3, 0.f);
                }
                C[(long)r * ldc + c]       = v0; C[(long)r * ldc + c + 1]       = v1;
                C[(long)(r + 8) * ldc + c] = v2; C[(long)(r + 8) * ldc + c + 1] = v3;
            }
        }
}

// h1 / a / b fused: share A=agg, K=512. 24 n-tile roles x 4 m-tiles = 96 CTAs.
__global__ __launch_bounds__(256)
void gemm3(const float* __restrict__ agg,
           const float* __restrict__ W1, const float* __restrict__ b1,
           const float* __restrict__ Ws1, const float* __restrict__ bs1)
{
    __shared__ unsigned sA[128*SA_LD];
    __shared__ unsigned sB[32*SB_LD];
    int tn = blockIdx.x % 24;
    int m0 = (blockIdx.x / 24) << 7;
    int grp = tn >> 3;
    int n0 = (tn & 7) << 7;
    const float* B; float* C; const float* bias; int mode;
    if (grp == 0)      { B = W1;               C = g_h1; bias = b1;  mode = 1; }
    else if (grp == 1) { B = Ws1;              C = g_a;  bias = bs1; mode = 0; }
    else               { B = Ws1 + 512 * 1024; C = g_b;  bias = 0;   mode = 0; }
    gemm_body(agg, 512, B, 1024, C, 1024, bias, 0, 512, m0, n0, mode, sA, sB);
}

// h2raw += h1 @ W2 (split-K x4): 16 tiles x 4 kslices = 64 CTAs
__global__ __launch_bounds__(256)
void gemm_h2(const float* __restrict__ W2)
{
    __shared__ unsigned sA[128*SA_LD];
    __shared__ unsigned sB[32*SB_LD];
    int t = blockIdx.x & 15;
    int ks = blockIdx.x >> 4;
    int m0 = (t >> 2) << 7;
    int n0 = (t & 3) << 7;
    gemm_body(g_h1, 1024, W2, 512, g_h2, 512, (const float*)0,
              ks * 256, ks * 256 + 256, m0, n0, 2, sA, sB);
}

// ---------------- Ws2 transpose fp32 -> fp16 [n][k] ----------------
__global__ void prep_ws2(const float* __restrict__ Ws2)
{
    __shared__ float tile[32][33];
    int bx = blockIdx.x, by = blockIdx.y;
    int tx = threadIdx.x, ty = threadIdx.y;
    #pragma unroll
    for (int r = 0; r < 32; r += 8)
        tile[ty + r][tx] = Ws2[(long)(by * 32 + ty + r) * HID2 + bx * 32 + tx];
    __syncthreads();
    #pragma unroll
    for (int r = 0; r < 32; r += 8)
        g_ws2t[(long)(bx * 32 + ty + r) * HID + by * 32 + tx] =
            __float2half_rn(tile[tx][ty + r]);
}

// zero g_logit (262144) + g_h2 raw accum (262144)
__global__ void zero_bufs()
{
    int i = blockIdx.x * blockDim.x + threadIdx.x;
    for (; i < NPAIRS * 2 + NROWS * HID2; i += gridDim.x * blockDim.x) {
        if (i < NPAIRS * 2) g_logit[i] = 0.f;
        else g_h2[i - NPAIRS * 2] = 0.f;
    }
}

// ---------------- per-segment epilogue (now applies b2+relu on raw h2) ------
__global__ void seg_epilogue(const float* __restrict__ W3,
                             const float* __restrict__ b3,
                             const float* __restrict__ b2,
                             const int* __restrict__ yw)
{
    int row = blockIdx.x;
    int lane = threadIdx.x;
    float s[6] = {0.f, 0.f, 0.f, 0.f, 0.f, 0.f};
    const float* hrow = g_h2 + (long)row * HID2;
    for (int k = lane; k < HID2; k += 32) {
        float h = fmaxf(hrow[k] + b2[k], 0.f);
        const float* w = W3 + k * 6;
        #pragma unroll
        for (int c = 0; c < 6; c++) s[c] += h * w[c];
    }
    #pragma unroll
    for (int off = 16; off > 0; off >>= 1)
        #pragma unroll
        for (int c = 0; c < 6; c++) s[c] += __shfl_xor_sync(0xffffffffu, s[c], off);

    if (lane == 0) {
        float l[6], m = -FLT_MAX;
        #pragma unroll
        for (int c = 0; c < 6; c++) { l[c] = s[c] + b3[c]; m = fmaxf(m, l[c]); }
        float se = 0.f;
        #pragma unroll
        for (int c = 0; c < 6; c++) se += expf(l[c] - m);
        float lse = m + logf(se);
        #pragma unroll
        for (int c = 0; c < 6; c++) g_hatp[row * 6 + c] = expf(l[c] - lse);

        int sum12 = 0;
        #pragma unroll
        for (int w = 0; w < 12; w++) sum12 += yw[w];
        int is64 = (sum12 == 1);
        int arg = 0;
        int bv = is64 ? yw[(row * 6) * 2] : yw[row * 6];
        #pragma unroll
        for (int c = 1; c < 6; c++) {
            int v = is64 ? yw[(row * 6 + c) * 2] : yw[row * 6 + c];
            if (v > bv) { bv = v; arg = c; }
        }
        g_segy[row] = arg;
        g_loss1_terms[row] = -(l[arg] - lse);
    }
}

// ---------------- fp16 pairwise GEMM (L2-traffic-fixed) ----------------
// CTA: 256 pairs (32 i x 8 j) x 128 n-cols, K=1024 in 16 chunks of 64.
// a/b row chunks staged in smem via cp.async (kills the 4.3GB L2 read stream),
// A tile generated from smem caches, B via cp.async; all double-buffered.
#define PPAD 72
#define ABUF (256*PPAD)               // halves (36864 B)
#define BBUF (128*PPAD)               // halves (18432 B)
#define AC_PITCH 72                   // floats per cached row (64 + 8 pad)
#define AC_BUF (32*AC_PITCH)          // floats (9216 B)
#define BC_BUF (8*AC_PITCH)           // floats (2304 B)
#define OFF_SA 0
#define OFF_SB (2*ABUF*2)             // 73728
#define OFF_AC (OFF_SB + 2*BBUF*2)    // 110592
#define OFF_BC (OFF_AC + 2*AC_BUF*4)  // 129024
#define OFF_BIAS (OFF_BC + 2*BC_BUF*4)// 133632
#define OFF_W3  (OFF_BIAS + 512)      // 134144
#define OFF_LP  (OFF_W3 + 1024)       // 135168
#define SMEM_PAIR (OFF_LP + 2048)     // 137216

__global__ __launch_bounds__(256, 1)
void pair_fp16(const float* __restrict__ bs2, const float* __restrict__ Ws3)
{
    extern __shared__ char smem[];
    __half* sA = (__half*)(smem + OFF_SA);
    float* aCache = (float*)(smem + OFF_AC);
    float* bCache = (float*)(smem + OFF_BC);
    float* sBias = (float*)(smem + OFF_BIAS);
    float* sW3   = (float*)(smem + OFF_W3);
    float* sLP   = (float*)(smem + OFF_LP);

    uint32_t sb_u32 = (uint32_t)__cvta_generic_to_shared(smem + OFF_SB);
    uint32_t ac_u32 = (uint32_t)__cvta_generic_to_shared(smem + OFF_AC);
    uint32_t bc_u32 = (uint32_t)__cvta_generic_to_shared(smem + OFF_BC);

    int tid = threadIdx.x, lane = tid & 31, warp = tid >> 5;
    int wm = warp & 3, wn = warp >> 2;
    int id = blockIdx.x;
    int nb = id & 3;
    int jt = (id >> 2) & 31;
    int it = (id >> 7) & 7;
    int bi = id >> 10;
    int i0 = it << 5, j0 = jt << 3, n0 = nb << 7;

    if (tid < 128) {
        sBias[tid] = bs2[n0 + tid];
        sW3[tid * 2]     = Ws3[(n0 + tid) * 2];
        sW3[tid * 2 + 1] = Ws3[(n0 + tid) * 2 + 1];
    }
    for (int t = tid; t < 512; t += 256) sLP[t] = 0.f;

    const float* ga = g_a + (long)(bi * 256 + i0) * HID;
    const float* gb = g_b + (long)(bi * 256 + j0) * HID;
    const __half* wsrc = g_ws2t + (long)n0 * HID;

    float acc[4][8][4];
    #pragma unroll
    for (int a = 0; a < 4; a++)
        #pragma unroll
        for (int b_ = 0; b_ < 8; b_++)
            #pragma unroll
            for (int c = 0; c < 4; c++) acc[a][b_][c] = 0.f;

    #define ISSUE_B(cc, bb) do {                                              \
        uint32_t dstb = sb_u32 + (bb)*BBUF*2;                                 \
        const __half* srcb = wsrc + (cc)*64;                                  \
        _Pragma("unroll")                                                     \
        for (int t = tid; t < 1024; t += 256) {                               \
            int n = t >> 3, seg = t & 7;                                      \
            asm volatile("cp.async.cg.shared.global [%0], [%1], 16;"          \
                :: "r"(dstb + n*144 + seg*16),                                \
                   "l"(srcb + (long)n*HID + seg*8) : "memory");               \
        }                                                                     \
    } while (0)

    #define ISSUE_CACHES(cc, bb) do {                                         \
        uint32_t adst = ac_u32 + (bb)*AC_BUF*4;                               \
        uint32_t bdst = bc_u32 + (bb)*BC_BUF*4;                               \
        const float* asrc = ga + (cc)*64;                                     \
        const float* bsrc = gb + (cc)*64;                                     \
        _Pragma("unroll")                                                     \
        for (int t = tid; t < 640; t += 256) {                                \
            if (t < 512) {                                                    \
                int r = t >> 4, sg = t & 15;                                  \
                asm volatile("cp.async.ca.shared.global [%0], [%1], 16;"      \
                    :: "r"(adst + r*288 + sg*16),                             \
                       "l"(asrc + (long)r*HID + sg*4) : "memory");            \
            } else {                                                          \
                int tt = t - 512; int r = tt >> 4, sg = tt & 15;              \
                asm volatile("cp.async.ca.shared.global [%0], [%1], 16;"      \
                    :: "r"(bdst + r*288 + sg*16),                             \
                       "l"(bsrc + (long)r*HID + sg*4) : "memory");            \
            }                                                                 \
        }                                                                     \
    } while (0)

    #define GEN_A(bb) do {                                                    \
        __half* abuf = sA + (bb)*ABUF;                                        \
        const float* ac = aCache + (bb)*AC_BUF;                               \
        const float* bc = bCache + (bb)*BC_BUF;                               \
        _Pragma("unroll")                                                     \
        for (int t = tid; t < 2048; t += 256) {                               \
            int p = t >> 3, seg = t & 7;                                      \
            int il = p >> 3, jl = p & 7;                                      \
            const float4* pa4 = (const float4*)(ac + il*AC_PITCH + seg*8);    \
            const float4* pb4 = (const float4*)(bc + jl*AC_PITCH + seg*8);    \
            float4 a0 = pa4[0], a1 = pa4[1];                                  \
            float4 b0 = pb4[0], b1 = pb4[1];                                  \
            uint4 v;                                                          \
            v.x = packh2(fmaxf(a0.x + b0.x, 0.f), fmaxf(a0.y + b0.y, 0.f));   \
            v.y = packh2(fmaxf(a0.z + b0.z, 0.f), fmaxf(a0.w + b0.w, 0.f));   \
            v.z = packh2(fmaxf(a1.x + b1.x, 0.f), fmaxf(a1.y + b1.y, 0.f));   \
            v.w = packh2(fmaxf(a1.z + b1.z, 0.f), fmaxf(a1.w + b1.w, 0.f));   \
            *(uint4*)((char*)abuf + p*144 + seg*16) = v;                      \
        }                                                                     \
    } while (0)

    // prolog
    ISSUE_B(0, 0);
    ISSUE_CACHES(0, 0);
    asm volatile("cp.async.commit_group;" ::: "memory");

    const unsigned* Aw = (const unsigned*)sA;
    const unsigned* Bw = (const unsigned*)(smem + OFF_SB);

    for (int c = 0; c < 16; c++) {
        int buf = c & 1;
        asm volatile("cp.async.wait_group 0;" ::: "memory");
        __syncthreads();
        GEN_A(buf);
        __syncthreads();
        if (c < 15) {
            ISSUE_B(c + 1, buf ^ 1);
            ISSUE_CACHES(c + 1, buf ^ 1);
            asm volatile("cp.async.commit_group;" ::: "memory");
        }
        // ---- MMA over buffer buf ----
        const unsigned* Ab = Aw + buf * (ABUF / 2);
        const unsigned* Bb = Bw + buf * (BBUF / 2);
        int r0 = wm * 64 + (lane >> 2);
        int c0 = lane & 3;
        #pragma unroll
        for (int ks = 0; ks < 4; ks++) {
            unsigned af[4][4], bf[8][2];
            #pragma unroll
            for (int mt = 0; mt < 4; mt++) {
                int r = r0 + mt * 16;
                const unsigned* base = Ab + ks * 8 + c0;
                af[mt][0] = base[r * 36];
                af[mt][1] = base[(r + 8) * 36];
                af[mt][2] = base[r * 36 + 4];
                af[mt][3] = base[(r + 8) * 36 + 4];
            }
            #pragma unroll
            for (int nt = 0; nt < 8; nt++) {
                int n = wn * 64 + nt * 8 + (lane >> 2);
                const unsigned* base = Bb + n * 36 + ks * 8 + c0;
                bf[nt][0] = base[0];
                bf[nt][1] = base[4];
            }
            #pragma unroll
            for (int mt = 0; mt < 4; mt++)
                #pragma unroll
                for (int nt = 0; nt < 8; nt++)
                    mma16(acc[mt][nt], af[mt], bf[nt]);
        }
    }

    // ---- epilogue: z=relu(acc+bs2), partial logits over this n-block ----
    float lp[4][2][2];
    #pragma unroll
    for (int mt = 0; mt < 4; mt++)
        #pragma unroll
        for (int h = 0; h < 2; h++) { lp[mt][h][0] = 0.f; lp[mt][h][1] = 0.f; }

    #pragma unroll
    for (int mt = 0; mt < 4; mt++)
        #pragma unroll
        for (int nt = 0; nt < 8; nt++) {
            int cl = wn * 64 + nt * 8 + ((lane & 3) << 1);
            float bz0 = sBias[cl], bz1 = sBias[cl + 1];
            float w00 = sW3[cl * 2],       w01 = sW3[cl * 2 + 1];
            float w10 = sW3[(cl + 1) * 2], w11 = sW3[(cl + 1) * 2 + 1];
            float z0 = fmaxf(acc[mt][nt][0] + bz0, 0.f);
            float z1 = fmaxf(acc[mt][nt][1] + bz1, 0.f);
            float z2 = fmaxf(acc[mt][nt][2] + bz0, 0.f);
            float z3 = fmaxf(acc[mt][nt][3] + bz1, 0.f);
            lp[mt][0][0] += z0 * w00 + z1 * w10;
            lp[mt][0][1] += z0 * w01 + z1 * w11;
            lp[mt][1][0] += z2 * w00 + z3 * w10;
            lp[mt][1][1] += z2 * w01 + z3 * w11;
        }
    #pragma unroll
    for (int off = 1; off < 4; off <<= 1)
        #pragma unroll
        for (int mt = 0; mt < 4; mt++)
            #pragma unroll
            for (int h = 0; h < 2; h++) {
                lp[mt][h][0] += __shfl_xor_sync(0xffffffffu, lp[mt][h][0], off);
                lp[mt][h][1] += __shfl_xor_sync(0xffffffffu, lp[mt][h][1], off);
            }
    if ((lane & 3) == 0) {
        #pragma unroll
        for (int mt = 0; mt < 4; mt++) {
            int p = wm * 64 + mt * 16 + (lane >> 2);
            atomicAdd(&sLP[p * 2],           lp[mt][0][0]);
            atomicAdd(&sLP[p * 2 + 1],       lp[mt][0][1]);
            atomicAdd(&sLP[(p + 8) * 2],     lp[mt][1][0]);
            atomicAdd(&sLP[(p + 8) * 2 + 1], lp[mt][1][1]);
        }
    }
    __syncthreads();
    for (int t = tid; t < 512; t += 256) {
        int p = t >> 1, s = t & 1;
        int i = i0 + (p >> 3), j = j0 + (p & 7);
        long flat = (long)(bi * 256 + i) * 256 + j;
        atomicAdd(&g_logit[flat * 2 + s], sLP[t]);
    }
    #undef ISSUE_B
    #undef ISSUE_CACHES
    #undef GEN_A
}

// ---------------- pairwise epilogue ----------------
__global__ void pair_epilogue(const float* __restrict__ bs3)
{
    int tid = threadIdx.x;
    int idx = blockIdx.x * 256 + tid;
    float l0 = g_logit[idx * 2]     + bs3[0];
    float l1 = g_logit[idx * 2 + 1] + bs3[1];
    float m = fmaxf(l0, l1);
    float e0 = expf(l0 - m), e1 = expf(l1 - m);
    float lse = m + logf(e0 + e1);
    float lq0 = l0 - lse, lq1 = l1 - lse;
    g_q1[idx] = expf(lq1);
    int bi = idx >> 16;
    int i = (idx >> 8) & 255, j = idx & 255;
    float sel = (g_segy[(bi << 8) + i] == g_segy[(bi << 8) + j]) ? lq1 : lq0;

    __shared__ float red[256];
    red[tid] = sel;
    __syncthreads();
    for (int s = 128; s > 0; s >>= 1) {
        if (tid < s) red[tid] += red[tid + s];
        __syncthreads();
    }
    if (tid == 0) g_loss2_part[blockIdx.x] = red[0];
}

__global__ void finalize_loss(float* __restrict__ out)
{
    int tid = threadIdx.x;
    __shared__ float r1[256], r2[256];
    r1[tid] = g_loss1_terms[tid] + g_loss1_terms[tid + 256];
    r2[tid] = g_loss2_part[tid] + g_loss2_part[tid + 256];
    __syncthreads();
    for (int s = 128; s > 0; s >>= 1) {
        if (tid < s) { r1[tid] += r1[tid + s]; r2[tid] += r2[tid + s]; }
        __syncthreads();
    }
    if (tid == 0) out[0] = r1[0] / 512.0f - r2[0] / 131072.0f;
}

__global__ void tilde_out(float* __restrict__ out)
{
    int row = blockIdx.x;
    int tid = threadIdx.x;
    int bi = row >> 8;
    float q = g_q1[(long)row * 256 + tid];
    const float* hp = g_hatp + (long)(bi * 256 + tid) * 6;

    __shared__ float sred[256][6];
    #pragma unroll
    for (int c = 0; c < 6; c++) sred[tid][c] = q * hp[c];
    __syncthreads();
    for (int s = 128; s > 0; s >>= 1) {
        if (tid < s)
            #pragma unroll
            for (int c = 0; c < 6; c++) sred[tid][c] += sred[tid + s][c];
        __syncthreads();
    }
    if (tid < 6) out[1 + row * 6 + tid] = g_hatp[row * 6 + tid];
    if (tid == 0) {
        float t = 0.f;
        #pragma unroll
        for (int c = 0; c < 6; c++) t += sred[0][c];
        #pragma unroll
        for (int c = 0; c < 6; c++) out[3073 + row * 6 + c] = sred[0][c] / t;
    }
    if (tid == 32) out[6145 + row] = (float)g_segy[row];
}

// ---------------- launch ----------------
extern "C" void kernel_launch(void* const* d_in, const int* in_sizes, int n_in,
                              void* d_out, int out_size)
{
    const float* agg = (const float*)d_in[0];
    const int*   yw  = (const int*)d_in[1];
    const float* W1  = (const float*)d_in[2];
    const float* b1  = (const float*)d_in[3];
    const float* W2  = (const float*)d_in[4];
    const float* b2  = (const float*)d_in[5];
    const float* W3  = (const float*)d_in[6];
    const float* b3  = (const float*)d_in[7];
    const float* Ws1 = (const float*)d_in[8];
    const float* bs1 = (const float*)d_in[9];
    const float* Ws2 = (const float*)d_in[10];
    const float* bs2 = (const float*)d_in[11];
    const float* Ws3 = (const float*)d_in[12];
    const float* bs3 = (const float*)d_in[13];
    float* out = (float*)d_out;

    static int cfg_done = 0;
    if (!cfg_done) {
        cudaFuncSetAttribute(pair_fp16,
                             cudaFuncAttributeMaxDynamicSharedMemorySize, SMEM_PAIR);
        cfg_done = 1;
    }

    zero_bufs<<<512, 256>>>();
    prep_ws2<<<dim3(16, 32), dim3(32, 8)>>>(Ws2);
    gemm3<<<96, 256>>>(agg, W1, b1, Ws1, bs1);
    gemm_h2<<<64, 256>>>(W2);
    seg_epilogue<<<512, 32>>>(W3, b3, b2, yw);
    pair_fp16<<<2048, 256, SMEM_PAIR>>>(bs2, Ws3);
    pair_epilogue<<<512, 256>>>(bs3);
    finalize_loss<<<1, 256>>>(out);
    tilde_out<<<512, 256>>>(out);
}

// round 5
// speedup vs baseline: 1.6327x; 1.6327x over previous
#include <cuda_runtime.h>
#include <cuda_fp16.h>
#include <math.h>
#include <float.h>
#include <stdint.h>

#define BDIM 2
#define NSEG 256
#define HID 1024
#define HID2 512
#define NCLS 6
#define NROWS 512
#define NPAIRS 131072

// ---------------- scratch ----------------
__device__ __half g_a16[NROWS*HID];       // fp16(agg @ Ws1[:D] + bs1)
__device__ __half g_b16[NROWS*HID];       // fp16(agg @ Ws1[D:])
__device__ float g_h1[NROWS*HID];
__device__ float g_h2[NROWS*HID2];        // RAW accum (pre-bias, pre-relu)
__device__ float g_hatp[NROWS*NCLS];
__device__ float g_loss1_terms[NROWS];
__device__ int   g_segy[NROWS];
__device__ float g_logit[NPAIRS*2];
__device__ float g_q1[NPAIRS];
__device__ float g_loss2_part[512];
__device__ __half g_ws2t[HID2*HID];       // [n][k] fp16 (transposed Ws2)

// ---------------- helpers ----------------
__device__ __forceinline__ unsigned f2tf32(float x) {
    unsigned r;
    asm("cvt.rna.tf32.f32 %0, %1;" : "=r"(r) : "f"(x));
    return r;
}
__device__ __forceinline__ void mma8(float* d, const unsigned* a, const unsigned* b) {
    asm volatile(
        "mma.sync.aligned.m16n8k8.row.col.f32.tf32.tf32.f32 "
        "{%0,%1,%2,%3}, {%4,%5,%6,%7}, {%8,%9}, {%0,%1,%2,%3};\n"
        : "+f"(d[0]), "+f"(d[1]), "+f"(d[2]), "+f"(d[3])
        : "r"(a[0]), "r"(a[1]), "r"(a[2]), "r"(a[3]), "r"(b[0]), "r"(b[1]));
}
__device__ __forceinline__ void mma16(float* d, const unsigned* a, const unsigned* b) {
    asm volatile(
        "mma.sync.aligned.m16n8k16.row.col.f32.f16.f16.f32 "
        "{%0,%1,%2,%3}, {%4,%5,%6,%7}, {%8,%9}, {%0,%1,%2,%3};\n"
        : "+f"(d[0]), "+f"(d[1]), "+f"(d[2]), "+f"(d[3])
        : "r"(a[0]), "r"(a[1]), "r"(a[2]), "r"(a[3]), "r"(b[0]), "r"(b[1]));
}
__device__ __forceinline__ unsigned packh2(float lo, float hi) {
    __half2 h = __floats2half2_rn(lo, hi);
    return *reinterpret_cast<unsigned*>(&h);
}
__device__ __forceinline__ unsigned addrelu2(unsigned a, unsigned b) {
    __half2 r = __hmax2(__hadd2(*(__half2*)&a, *(__half2*)&b),
                        __float2half2_rn(0.f));
    return *reinterpret_cast<unsigned*>(&r);
}

#define SA_LD 36
#define SB_LD 136

// ---------------- generic tf32 GEMM body (128x128 tile) ----------------
// mode: 0 = f32 store (+bias), 1 = f32 store (+bias, relu),
//       2 = f32 atomicAdd raw, 3 = half store (+bias)
__device__ __forceinline__ void gemm_body(
    const float* __restrict__ A, int lda, const float* __restrict__ B, int ldb,
    float* __restrict__ C, __half* __restrict__ Ch, int ldc,
    const float* __restrict__ bias,
    int kbeg, int kend, int m0, int n0, int mode, unsigned* sA, unsigned* sB)
{
    int tid = threadIdx.x;
    int lane = tid & 31, warp = tid >> 5;
    int wm = warp & 3, wn = warp >> 2;

    float acc[2][8][4];
    #pragma unroll
    for (int a = 0; a < 2; a++)
        #pragma unroll
        for (int b_ = 0; b_ < 8; b_++)
            #pragma unroll
            for (int c = 0; c < 4; c++) acc[a][b_][c] = 0.f;

    for (int k0 = kbeg; k0 < kend; k0 += 32) {
        __syncthreads();
        #pragma unroll
        for (int s = tid; s < 1024; s += 256) {
            int row = s >> 3, cv = (s & 7) << 2;
            float4 v = *(const float4*)(A + (long)(m0 + row) * lda + k0 + cv);
            unsigned* p = &sA[row * SA_LD + cv];
            p[0] = f2tf32(v.x); p[1] = f2tf32(v.y); p[2] = f2tf32(v.z); p[3] = f2tf32(v.w);
        }
        #pragma unroll
        for (int s = tid; s < 1024; s += 256) {
            int row = s >> 5, cv = (s & 31) << 2;
            float4 v = *(const float4*)(B + (long)(k0 + row) * ldb + n0 + cv);
            unsigned* p = &sB[row * SB_LD + cv];
            p[0] = f2tf32(v.x); p[1] = f2tf32(v.y); p[2] = f2tf32(v.z); p[3] = f2tf32(v.w);
        }
        __syncthreads();
        #pragma unroll
        for (int ks = 0; ks < 4; ks++) {
            int k = ks << 3;
            unsigned af[2][4], bf[8][2];
            #pragma unroll
            for (int mi = 0; mi < 2; mi++) {
                int r = wm * 32 + mi * 16 + (lane >> 2);
                int c = k + (lane & 3);
                af[mi][0] = sA[r * SA_LD + c];
                af[mi][1] = sA[(r + 8) * SA_LD + c];
                af[mi][2] = sA[r * SA_LD + c + 4];
                af[mi][3] = sA[(r + 8) * SA_LD + c + 4];
            }
            #pragma unroll
            for (int ni = 0; ni < 8; ni++) {
                int c = wn * 64 + ni * 8 + (lane >> 2);
                int r = k + (lane & 3);
                bf[ni][0] = sB[r * SB_LD + c];
                bf[ni][1] = sB[(r + 4) * SB_LD + c];
            }
            #pragma unroll
            for (int mi = 0; mi < 2; mi++)
                #pragma unroll
                for (int ni = 0; ni < 8; ni++)
                    mma8(acc[mi][ni], af[mi], bf[ni]);
        }
    }

    #pragma unroll
    for (int mi = 0; mi < 2; mi++)
        #pragma unroll
        for (int ni = 0; ni < 8; ni++) {
            int r = m0 + wm * 32 + mi * 16 + (lane >> 2);
            int c = n0 + wn * 64 + ni * 8 + ((lane & 3) << 1);
            if (mode == 2) {
                atomicAdd(&C[(long)r * ldc + c],           acc[mi][ni][0]);
                atomicAdd(&C[(long)r * ldc + c + 1],       acc[mi][ni][1]);
                atomicAdd(&C[(long)(r + 8) * ldc + c],     acc[mi][ni][2]);
                atomicAdd(&C[(long)(r + 8) * ldc + c + 1], acc[mi][ni][3]);
            } else {
                float b0 = bias ? bias[c] : 0.f;
                float b1 = bias ? bias[c + 1] : 0.f;
                float v0 = acc[mi][ni][0] + b0, v1 = acc[mi][ni][1] + b1;
                float v2 = acc[mi][ni][2] + b0, v3 = acc[mi][ni][3] + b1;
                if (mode == 1) {
                    v0 = fmaxf(v0, 0.f); v1 = fmaxf(v1, 0.f);
                    v2 = fmaxf(v2, 0.f); v3 = fmaxf(v3, 0.f);
                }
                if (mode == 3) {
                    *(unsigned*)&Ch[(long)r * ldc + c]       = packh2(v0, v1);
                    *(unsigned*)&Ch[(long)(r + 8) * ldc + c] = packh2(v2, v3);
                } else {
                    C[(long)r * ldc + c]       = v0; C[(long)r * ldc + c + 1]       = v1;
                    C[(long)(r + 8) * ldc + c] = v2; C[(long)(r + 8) * ldc + c + 1] = v3;
                }
            }
        }
}

// h1 / a16 / b16 fused: share A=agg, K=512. 24 roles x 4 m-tiles = 96 CTAs.
__global__ __launch_bounds__(256)
void gemm3(const float* __restrict__ agg,
           const float* __restrict__ W1, const float* __restrict__ b1,
           const float* __restrict__ Ws1, const float* __restrict__ bs1)
{
    __shared__ unsigned sA[128*SA_LD];
    __shared__ unsigned sB[32*SB_LD];
    int tn = blockIdx.x % 24;
    int m0 = (blockIdx.x / 24) << 7;
    int grp = tn >> 3;
    int n0 = (tn & 7) << 7;
    if (grp == 0)
        gemm_body(agg, 512, W1, 1024, g_h1, (half*)0, 1024, b1, 0, 512, m0, n0, 1, sA, sB);
    else if (grp == 1)
        gemm_body(agg, 512, Ws1, 1024, (float*)0, g_a16, 1024, bs1, 0, 512, m0, n0, 3, sA, sB);
    else
        gemm_body(agg, 512, Ws1 + 512 * 1024, 1024, (float*)0, g_b16, 1024,
                  (const float*)0, 0, 512, m0, n0, 3, sA, sB);
}

// h2raw += h1 @ W2 (split-K x8): 16 tiles x 8 kslices = 128 CTAs
__global__ __launch_bounds__(256)
void gemm_h2(const float* __restrict__ W2)
{
    __shared__ unsigned sA[128*SA_LD];
    __shared__ unsigned sB[32*SB_LD];
    int t = blockIdx.x & 15;
    int ks = blockIdx.x >> 4;
    int m0 = (t >> 2) << 7;
    int n0 = (t & 3) << 7;
    gemm_body(g_h1, 1024, W2, 512, g_h2, (half*)0, 512, (const float*)0,
              ks * 128, ks * 128 + 128, m0, n0, 2, sA, sB);
}

// ---------------- Ws2 transpose fp32 -> fp16 [n][k] ----------------
__global__ void prep_ws2(const float* __restrict__ Ws2)
{
    __shared__ float tile[32][33];
    int bx = blockIdx.x, by = blockIdx.y;
    int tx = threadIdx.x, ty = threadIdx.y;
    #pragma unroll
    for (int r = 0; r < 32; r += 8)
        tile[ty + r][tx] = Ws2[(long)(by * 32 + ty + r) * HID2 + bx * 32 + tx];
    __syncthreads();
    #pragma unroll
    for (int r = 0; r < 32; r += 8)
        g_ws2t[(long)(bx * 32 + ty + r) * HID + by * 32 + tx] =
            __float2half_rn(tile[tx][ty + r]);
}

__global__ void zero_bufs()
{
    int i = blockIdx.x * blockDim.x + threadIdx.x;
    for (; i < NPAIRS * 2 + NROWS * HID2; i += gridDim.x * blockDim.x) {
        if (i < NPAIRS * 2) g_logit[i] = 0.f;
        else g_h2[i - NPAIRS * 2] = 0.f;
    }
}

// ---------------- per-segment epilogue (applies b2+relu on raw h2) ----------
__global__ void seg_epilogue(const float* __restrict__ W3,
                             const float* __restrict__ b3,
                             const float* __restrict__ b2,
                             const int* __restrict__ yw)
{
    int row = blockIdx.x;
    int lane = threadIdx.x;
    float s[6] = {0.f, 0.f, 0.f, 0.f, 0.f, 0.f};
    const float* hrow = g_h2 + (long)row * HID2;
    for (int k = lane; k < HID2; k += 32) {
        float h = fmaxf(hrow[k] + b2[k], 0.f);
        const float* w = W3 + k * 6;
        #pragma unroll
        for (int c = 0; c < 6; c++) s[c] += h * w[c];
    }
    #pragma unroll
    for (int off = 16; off > 0; off >>= 1)
        #pragma unroll
        for (int c = 0; c < 6; c++) s[c] += __shfl_xor_sync(0xffffffffu, s[c], off);

    if (lane == 0) {
        float l[6], m = -FLT_MAX;
        #pragma unroll
        for (int c = 0; c < 6; c++) { l[c] = s[c] + b3[c]; m = fmaxf(m, l[c]); }
        float se = 0.f;
        #pragma unroll
        for (int c = 0; c < 6; c++) se += expf(l[c] - m);
        float lse = m + logf(se);
        #pragma unroll
        for (int c = 0; c < 6; c++) g_hatp[row * 6 + c] = expf(l[c] - lse);

        int sum12 = 0;
        #pragma unroll
        for (int w = 0; w < 12; w++) sum12 += yw[w];
        int is64 = (sum12 == 1);
        int arg = 0;
        int bv = is64 ? yw[(row * 6) * 2] : yw[row * 6];
        #pragma unroll
        for (int c = 1; c < 6; c++) {
            int v = is64 ? yw[(row * 6 + c) * 2] : yw[row * 6 + c];
            if (v > bv) { bv = v; arg = c; }
        }
        g_segy[row] = arg;
        g_loss1_terms[row] = -(l[arg] - lse);
    }
}

// ---------------- fp16 pairwise GEMM: register A-gen, 2 CTA/SM ----------------
// CTA: 128 pairs (16 i x 8 j) x 128 n-cols, K=1024 in 16 chunks of 64.
// A fragments built in registers from fp16 a/b caches in smem (no A tile).
#define POF_B    0                        // 2 x 128x144 = 36864
#define POF_A2   36864                    // 2 x 16x144 = 4608
#define POF_B2   41472                    // 2 x 8x144  = 2304
#define POF_BIAS 43776                    // 512
#define POF_W3   44288                    // 1024
#define POF_LP   45312                    // 1024
#define PSMEM    46336

__global__ void __launch_bounds__(256, 2)
pair_fp16(const float* __restrict__ bs2, const float* __restrict__ Ws3)
{
    extern __shared__ char smem[];
    float* sBias = (float*)(smem + POF_BIAS);
    float* sW3   = (float*)(smem + POF_W3);
    float* sLP   = (float*)(smem + POF_LP);

    uint32_t u_b  = (uint32_t)__cvta_generic_to_shared(smem + POF_B);
    uint32_t u_a2 = (uint32_t)__cvta_generic_to_shared(smem + POF_A2);
    uint32_t u_b2 = (uint32_t)__cvta_generic_to_shared(smem + POF_B2);

    int tid = threadIdx.x, lane = tid & 31, warp = tid >> 5;
    int wm = warp & 3, wn = warp >> 2;
    int id = blockIdx.x;
    int nb = id & 3;
    int jt = (id >> 2) & 31;
    int it = (id >> 7) & 15;
    int bi = id >> 11;
    int i0 = it << 4, j0 = jt << 3, n0 = nb << 7;

    if (tid < 128) {
        sBias[tid] = bs2[n0 + tid];
        sW3[tid * 2]     = Ws3[(n0 + tid) * 2];
        sW3[tid * 2 + 1] = Ws3[(n0 + tid) * 2 + 1];
    }
    if (tid < 128) { sLP[tid] = 0.f; sLP[tid + 128] = 0.f; }

    const __half* ga = g_a16 + (long)(bi * 256 + i0) * HID;   // 16 rows
    const __half* gb = g_b16 + (long)(bi * 256 + j0) * HID;   // 8 rows
    const __half* wsrc = g_ws2t + (long)n0 * HID;             // 128 rows

    float acc[2][8][4];
    #pragma unroll
    for (int a = 0; a < 2; a++)
        #pragma unroll
        for (int b_ = 0; b_ < 8; b_++)
            #pragma unroll
            for (int c = 0; c < 4; c++) acc[a][b_][c] = 0.f;

    #define ISSUE(cc, bb) do {                                                \
        int k0h = (cc) * 64;                                                  \
        _Pragma("unroll")                                                     \
        for (int t = tid; t < 1216; t += 256) {                               \
            if (t < 1024) {                                                   \
                int n = t >> 3, seg = t & 7;                                  \
                asm volatile("cp.async.cg.shared.global [%0], [%1], 16;"      \
                    :: "r"(u_b + (bb)*18432 + n*144 + seg*16),                \
                       "l"(wsrc + (long)n*HID + k0h + seg*8) : "memory");     \
            } else if (t < 1152) {                                            \
                int u = t - 1024; int r = u >> 3, seg = u & 7;                \
                asm volatile("cp.async.ca.shared.global [%0], [%1], 16;"      \
                    :: "r"(u_a2 + (bb)*2304 + r*144 + seg*16),                \
                       "l"(ga + (long)r*HID + k0h + seg*8) : "memory");       \
            } else {                                                          \
                int u = t - 1152; int r = u >> 3, seg = u & 7;                \
                asm volatile("cp.async.ca.shared.global [%0], [%1], 16;"      \
                    :: "r"(u_b2 + (bb)*1152 + r*144 + seg*16),                \
                       "l"(gb + (long)r*HID + k0h + seg*8) : "memory");       \
            }                                                                 \
        }                                                                     \
        asm volatile("cp.async.commit_group;" ::: "memory");                  \
    } while (0)

    // prolog
    ISSUE(0, 0);

    int c0 = lane & 3;
    int jl = lane >> 2;

    for (int c = 0; c < 16; c++) {
        int buf = c & 1;
        if (c < 15) {
            ISSUE(c + 1, buf ^ 1);
            asm volatile("cp.async.wait_group 1;" ::: "memory");
        } else {
            asm volatile("cp.async.wait_group 0;" ::: "memory");
        }
        __syncthreads();

        const unsigned* Bb = (const unsigned*)(smem + POF_B  + buf * 18432);
        const unsigned* A2 = (const unsigned*)(smem + POF_A2 + buf * 2304);
        const unsigned* B2 = (const unsigned*)(smem + POF_B2 + buf * 1152);

        #pragma unroll
        for (int ks = 0; ks < 4; ks++) {
            unsigned bv0 = B2[jl * 36 + ks * 8 + c0];
            unsigned bv1 = B2[jl * 36 + ks * 8 + 4 + c0];
            unsigned af[2][4], bf[8][2];
            #pragma unroll
            for (int mi = 0; mi < 2; mi++) {
                int base = (wm * 4 + mi * 2) * 36 + ks * 8 + c0;
                af[mi][0] = addrelu2(A2[base],          bv0);
                af[mi][1] = addrelu2(A2[base + 36],     bv0);
                af[mi][2] = addrelu2(A2[base + 4],      bv1);
                af[mi][3] = addrelu2(A2[base + 36 + 4], bv1);
            }
            #pragma unroll
            for (int nt = 0; nt < 8; nt++) {
                int n = wn * 64 + nt * 8 + (lane >> 2);
                const unsigned* basep = Bb + n * 36 + ks * 8 + c0;
                bf[nt][0] = basep[0];
                bf[nt][1] = basep[4];
            }
            #pragma unroll
            for (int mi = 0; mi < 2; mi++)
                #pragma unroll
                for (int nt = 0; nt < 8; nt++)
                    mma16(acc[mi][nt], af[mi], bf[nt]);
        }
        __syncthreads();
    }

    // ---- epilogue: z=relu(acc+bs2), partial logits over this n-block ----
    float lp[2][2][2];
    #pragma unroll
    for (int mi = 0; mi < 2; mi++)
        #pragma unroll
        for (int h = 0; h < 2; h++) { lp[mi][h][0] = 0.f; lp[mi][h][1] = 0.f; }

    #pragma unroll
    for (int mi = 0; mi < 2; mi++)
        #pragma unroll
        for (int nt = 0; nt < 8; nt++) {
            int cl = wn * 64 + nt * 8 + ((lane & 3) << 1);
            float bz0 = sBias[cl], bz1 = sBias[cl + 1];
            float w00 = sW3[cl * 2],       w01 = sW3[cl * 2 + 1];
            float w10 = sW3[(cl + 1) * 2], w11 = sW3[(cl + 1) * 2 + 1];
            float z0 = fmaxf(acc[mi][nt][0] + bz0, 0.f);
            float z1 = fmaxf(acc[mi][nt][1] + bz1, 0.f);
            float z2 = fmaxf(acc[mi][nt][2] + bz0, 0.f);
            float z3 = fmaxf(acc[mi][nt][3] + bz1, 0.f);
            lp[mi][0][0] += z0 * w00 + z1 * w10;
            lp[mi][0][1] += z0 * w01 + z1 * w11;
            lp[mi][1][0] += z2 * w00 + z3 * w10;
            lp[mi][1][1] += z2 * w01 + z3 * w11;
        }
    #pragma unroll
    for (int off = 1; off < 4; off <<= 1)
        #pragma unroll
        for (int mi = 0; mi < 2; mi++)
            #pragma unroll
            for (int h = 0; h < 2; h++) {
                lp[mi][h][0] += __shfl_xor_sync(0xffffffffu, lp[mi][h][0], off);
                lp[mi][h][1] += __shfl_xor_sync(0xffffffffu, lp[mi][h][1], off);
            }
    if ((lane & 3) == 0) {
        #pragma unroll
        for (int mi = 0; mi < 2; mi++) {
            int p = wm * 32 + mi * 16 + (lane >> 2);
            atomicAdd(&sLP[p * 2],           lp[mi][0][0]);
            atomicAdd(&sLP[p * 2 + 1],       lp[mi][0][1]);
            atomicAdd(&sLP[(p + 8) * 2],     lp[mi][1][0]);
            atomicAdd(&sLP[(p + 8) * 2 + 1], lp[mi][1][1]);
        }
    }
    __syncthreads();
    {
        int p = tid >> 1, s = tid & 1;
        int i = i0 + (p >> 3), j = j0 + (p & 7);
        long flat = (long)(bi * 256 + i) * 256 + j;
        atomicAdd(&g_logit[flat * 2 + s], sLP[tid]);
    }
    #undef ISSUE
}

// ---------------- pairwise epilogue ----------------
__global__ void pair_epilogue(const float* __restrict__ bs3)
{
    int tid = threadIdx.x;
    int idx = blockIdx.x * 256 + tid;
    float l0 = g_logit[idx * 2]     + bs3[0];
    float l1 = g_logit[idx * 2 + 1] + bs3[1];
    float m = fmaxf(l0, l1);
    float e0 = expf(l0 - m), e1 = expf(l1 - m);
    float lse = m + logf(e0 + e1);
    float lq0 = l0 - lse, lq1 = l1 - lse;
    g_q1[idx] = expf(lq1);
    int bi = idx >> 16;
    int i = (idx >> 8) & 255, j = idx & 255;
    float sel = (g_segy[(bi << 8) + i] == g_segy[(bi << 8) + j]) ? lq1 : lq0;

    __shared__ float red[256];
    red[tid] = sel;
    __syncthreads();
    for (int s = 128; s > 0; s >>= 1) {
        if (tid < s) red[tid] += red[tid + s];
        __syncthreads();
    }
    if (tid == 0) g_loss2_part[blockIdx.x] = red[0];
}

__global__ void finalize_loss(float* __restrict__ out)
{
    int tid = threadIdx.x;
    __shared__ float r1[256], r2[256];
    r1[tid] = g_loss1_terms[tid] + g_loss1_terms[tid + 256];
    r2[tid] = g_loss2_part[tid] + g_loss2_part[tid + 256];
    __syncthreads();
    for (int s = 128; s > 0; s >>= 1) {
        if (tid < s) { r1[tid] += r1[tid + s]; r2[tid] += r2[tid + s]; }
        __syncthreads();
    }
    if (tid == 0) out[0] = r1[0] / 512.0f - r2[0] / 131072.0f;
}

__global__ void tilde_out(float* __restrict__ out)
{
    int row = blockIdx.x;
    int tid = threadIdx.x;
    int bi = row >> 8;
    float q = g_q1[(long)row * 256 + tid];
    const float* hp = g_hatp + (long)(bi * 256 + tid) * 6;

    __shared__ float sred[256][6];
    #pragma unroll
    for (int c = 0; c < 6; c++) sred[tid][c] = q * hp[c];
    __syncthreads();
    for (int s = 128; s > 0; s >>= 1) {
        if (tid < s)
            #pragma unroll
            for (int c = 0; c < 6; c++) sred[tid][c] += sred[tid + s][c];
        __syncthreads();
    }
    if (tid < 6) out[1 + row * 6 + tid] = g_hatp[row * 6 + tid];
    if (tid == 0) {
        float t = 0.f;
        #pragma unroll
        for (int c = 0; c < 6; c++) t += sred[0][c];
        #pragma unroll
        for (int c = 0; c < 6; c++) out[3073 + row * 6 + c] = sred[0][c] / t;
    }
    if (tid == 32) out[6145 + row] = (float)g_segy[row];
}

// ---------------- launch ----------------
extern "C" void kernel_launch(void* const* d_in, const int* in_sizes, int n_in,
                              void* d_out, int out_size)
{
    const float* agg = (const float*)d_in[0];
    const int*   yw  = (const int*)d_in[1];
    const float* W1  = (const float*)d_in[2];
    const float* b1  = (const float*)d_in[3];
    const float* W2  = (const float*)d_in[4];
    const float* b2  = (const float*)d_in[5];
    const float* W3  = (const float*)d_in[6];
    const float* b3  = (const float*)d_in[7];
    const float* Ws1 = (const float*)d_in[8];
    const float* bs1 = (const float*)d_in[9];
    const float* Ws2 = (const float*)d_in[10];
    const float* bs2 = (const float*)d_in[11];
    const float* Ws3 = (const float*)d_in[12];
    const float* bs3 = (const float*)d_in[13];
    float* out = (float*)d_out;

    static int cfg_done = 0;
    if (!cfg_done) {
        cudaFuncSetAttribute(pair_fp16,
                             cudaFuncAttributeMaxDynamicSharedMemorySize, PSMEM);
        cfg_done = 1;
    }

    zero_bufs<<<512, 256>>>();
    prep_ws2<<<dim3(16, 32), dim3(32, 8)>>>(Ws2);
    gemm3<<<96, 256>>>(agg, W1, b1, Ws1, bs1);
    gemm_h2<<<128, 256>>>(W2);
    seg_epilogue<<<512, 32>>>(W3, b3, b2, yw);
    pair_fp16<<<4096, 256, PSMEM>>>(bs2, Ws3);
    pair_epilogue<<<512, 256>>>(bs3);
    finalize_loss<<<1, 256>>>(out);
    tilde_out<<<512, 256>>>(out);
}